// round 4
// baseline (speedup 1.0000x reference)
#include <cuda_runtime.h>
#include <cstdint>

// Problem constants
#define NB      16
#define LD      64          // L (embedding dim)
#define HWD     4096        // H*W
#define NROWS   65536       // B*H*W
#define KCODES  1024
#define ELEMS   4194304     // B*L*H*W
#define KT      128         // codes per smem tile
#define TPB2    64          // threads per block, argmin kernel
#define GATHER_BLOCKS 16384 // ELEMS / 256

// Scratch (static device allocations only — no runtime alloc)
__device__ int    g_idx[NROWS];
__device__ float  g_en2[KCODES];
__device__ double g_part[GATHER_BLOCKS];

// ---------------------------------------------------------------------------
// K1: per-code squared norms. Separate mul/add rounding (no FMA contraction),
// sequential order — matches jnp.sum(emb*emb, axis=1) to sub-ulp.
// ---------------------------------------------------------------------------
__global__ void en2_kernel(const float* __restrict__ emb) {
    int k = blockIdx.x * blockDim.x + threadIdx.x;
    if (k < KCODES) {
        const float* e = emb + k * LD;
        float s = 0.0f;
#pragma unroll
        for (int l = 0; l < LD; l++)
            s = __fadd_rn(s, __fmul_rn(e[l], e[l]));
        g_en2[k] = s;
    }
}

// ---------------------------------------------------------------------------
// K2: argmin over codes. Replicates reference numerics:
//   d_k = fl( fl(a + b_k) - 2*m_k ), a = sum zf^2 (mul+add, sequential),
//   m_k = sequential fp32 FMA chain over l (cuBLAS-style), 2*m exact.
// Strict '<' scan in ascending k => first-min tie-break like jnp.argmin.
// ---------------------------------------------------------------------------
__global__ void __launch_bounds__(TPB2)
argmin_kernel(const float* __restrict__ ze, const float* __restrict__ emb,
              float* __restrict__ out_idx) {
    __shared__ float se[KT * LD];      // 32 KB code tile
    __shared__ float sen2[KT];

    int n  = blockIdx.x * TPB2 + threadIdx.x;   // row id (b,h,w)
    int b  = n >> 12;
    int hw = n & 4095;

    // Load this row's zf into registers: ze[b][l][h][w], coalesced across hw.
    const float* zb = ze + (size_t)(b * LD) * HWD + hw;
    float zf[LD];
#pragma unroll
    for (int l = 0; l < LD; l++) zf[l] = zb[(size_t)l * HWD];

    // a = ||zf||^2, separate-rounded, sequential
    float a = 0.0f;
#pragma unroll
    for (int l = 0; l < LD; l++) a = __fadd_rn(a, __fmul_rn(zf[l], zf[l]));

    float best = __int_as_float(0x7f800000);  // +inf
    int   bi   = 0;

    for (int t = 0; t < KCODES / KT; t++) {
        __syncthreads();
        // Cooperative tile load: 2048 float4 by 64 threads = 32 each, coalesced
        {
            const float4* src = (const float4*)(emb + t * KT * LD);
            float4*       dst = (float4*)se;
#pragma unroll
            for (int i = 0; i < (KT * LD / 4) / TPB2; i++)
                dst[threadIdx.x + i * TPB2] = src[threadIdx.x + i * TPB2];
#pragma unroll
            for (int i = 0; i < KT / TPB2; i++)
                sen2[threadIdx.x + i * TPB2] = g_en2[t * KT + threadIdx.x + i * TPB2];
        }
        __syncthreads();

        // Two codes at a time: two independent 64-deep FMA chains for ILP.
        for (int kk = 0; kk < KT; kk += 2) {
            const float4* e0 = (const float4*)(se + (kk    ) * LD);
            const float4* e1 = (const float4*)(se + (kk + 1) * LD);
            float m0 = 0.0f, m1 = 0.0f;
#pragma unroll
            for (int j = 0; j < 16; j++) {
                float4 v0 = e0[j];
                float4 v1 = e1[j];
                m0 = __fmaf_rn(zf[4*j+0], v0.x, m0);  m1 = __fmaf_rn(zf[4*j+0], v1.x, m1);
                m0 = __fmaf_rn(zf[4*j+1], v0.y, m0);  m1 = __fmaf_rn(zf[4*j+1], v1.y, m1);
                m0 = __fmaf_rn(zf[4*j+2], v0.z, m0);  m1 = __fmaf_rn(zf[4*j+2], v1.z, m1);
                m0 = __fmaf_rn(zf[4*j+3], v0.w, m0);  m1 = __fmaf_rn(zf[4*j+3], v1.w, m1);
            }
            // d = fl( fl(a + en2) + (-2*m) ); -2*m is exact in fp32
            float d0 = __fadd_rn(__fadd_rn(a, sen2[kk    ]), __fmul_rn(-2.0f, m0));
            float d1 = __fadd_rn(__fadd_rn(a, sen2[kk + 1]), __fmul_rn(-2.0f, m1));
            int k0 = t * KT + kk;
            if (d0 < best) { best = d0; bi = k0;     }
            if (d1 < best) { best = d1; bi = k0 + 1; }
        }
    }

    g_idx[n]   = bi;
    out_idx[n] = (float)bi;   // idx output region (cast to output dtype)
}

// ---------------------------------------------------------------------------
// K3: gather z_q, emit z_q_st = ze + (z_q - ze) in reference op order,
// accumulate per-block double partial sums of fl32((z_q - ze)^2).
// ---------------------------------------------------------------------------
__global__ void __launch_bounds__(256)
gather_kernel(const float* __restrict__ ze, const float* __restrict__ emb,
              float* __restrict__ out) {
    __shared__ double ssum[256];
    int i   = blockIdx.x * 256 + threadIdx.x;   // linear (b,l,h,w)
    int b   = i >> 18;                          // 64*4096 = 262144 per b
    int rem = i & 262143;
    int l   = rem >> 12;
    int hw  = rem & 4095;
    int n   = (b << 12) | hw;

    int   k   = g_idx[n];
    float zev = ze[i];
    float zq  = emb[k * LD + l];
    float t   = __fadd_rn(zq, -zev);     // z_q - ze   (fp32, as reference)
    out[i]    = __fadd_rn(zev, t);       // ze + (z_q - ze)
    float t2  = __fmul_rn(t, t);

    ssum[threadIdx.x] = (double)t2;
    __syncthreads();
#pragma unroll
    for (int s = 128; s > 0; s >>= 1) {
        if (threadIdx.x < s) ssum[threadIdx.x] += ssum[threadIdx.x + s];
        __syncthreads();
    }
    if (threadIdx.x == 0) g_part[blockIdx.x] = ssum[0];
}

// ---------------------------------------------------------------------------
// K4: deterministic final reduction -> loss = 1.25 * mean((z_q - ze)^2)
// ---------------------------------------------------------------------------
__global__ void __launch_bounds__(256)
loss_kernel(float* __restrict__ out) {
    __shared__ double ssum[256];
    double s = 0.0;
    for (int i = threadIdx.x; i < GATHER_BLOCKS; i += 256) s += g_part[i];
    ssum[threadIdx.x] = s;
    __syncthreads();
#pragma unroll
    for (int st = 128; st > 0; st >>= 1) {
        if (threadIdx.x < st) ssum[threadIdx.x] += ssum[threadIdx.x + st];
        __syncthreads();
    }
    if (threadIdx.x == 0) {
        double m = ssum[0] / (double)ELEMS;
        out[ELEMS] = (float)(m * 1.25);   // loss scalar slot
    }
}

// ---------------------------------------------------------------------------
// Launch. Outputs concatenated: [z_q_st (4194304)] [loss (1)] [idx (65536)]
// ---------------------------------------------------------------------------
extern "C" void kernel_launch(void* const* d_in, const int* in_sizes, int n_in,
                              void* d_out, int out_size) {
    const float* ze  = (const float*)d_in[0];   // 4194304
    const float* emb = (const float*)d_in[1];   // 65536
    float* out = (float*)d_out;
    float* out_idx = out + ELEMS + 1;

    en2_kernel   <<<(KCODES + 255) / 256, 256>>>(emb);
    argmin_kernel<<<NROWS / TPB2, TPB2>>>(ze, emb, out_idx);
    gather_kernel<<<GATHER_BLOCKS, 256>>>(ze, emb, out);
    loss_kernel  <<<1, 256>>>(out);
}

// round 5
// speedup vs baseline: 1.2383x; 1.2383x over previous
#include <cuda_runtime.h>
#include <cstdint>

// Problem constants
#define NB      16
#define LD      64          // L (embedding dim)
#define HWD     4096        // H*W
#define NROWS   65536       // B*H*W
#define KCODES  1024
#define ELEMS   4194304     // B*L*H*W
#define KT      128         // codes per smem tile
#define TPB2    64          // threads per block, argmin kernel

// Scratch (static device allocations only)
__device__ int    g_idx[NROWS];
__device__ float  g_en2[KCODES];
__device__ double g_loss;

// Packed fp32x2 FMA: two independent round-to-nearest fp32 FMAs per instr.
// Bit-identical per lane to scalar __fmaf_rn — preserves exact argmin numerics.
#define FMA_F32X2(d, a, b, c) \
    asm("fma.rn.f32x2 %0, %1, %2, %3;" : "=l"(d) : "l"(a), "l"(b), "l"(c))
#define PACK2(out, lo, hi) \
    asm("mov.b64 %0, {%1, %2};" : "=l"(out) : "r"(lo), "r"(hi))
#define UNPACK2(lo, hi, in) \
    asm("mov.b64 {%0, %1}, %2;" : "=r"(lo), "=r"(hi) : "l"(in))

// ---------------------------------------------------------------------------
// K1: per-code squared norms (separate mul/add rounding, sequential order —
// matches jnp.sum(emb*emb, axis=1) exactly). Also zeroes the loss accumulator.
// ---------------------------------------------------------------------------
__global__ void en2_kernel(const float* __restrict__ emb) {
    int k = blockIdx.x * blockDim.x + threadIdx.x;
    if (k == 0) g_loss = 0.0;
    if (k < KCODES) {
        const float* e = emb + k * LD;
        float s = 0.0f;
#pragma unroll
        for (int l = 0; l < LD; l++)
            s = __fadd_rn(s, __fmul_rn(e[l], e[l]));
        g_en2[k] = s;
    }
}

// ---------------------------------------------------------------------------
// K2: argmin over codes, FFMA2 path.
//   d_k = fl( fl(a + b_k) - 2*m_k ),  m_k = sequential fp32 FMA chain over l.
//   Two code-chains ride the lo/hi halves of one f32x2 register; each chain
//   is the exact sequential scalar chain -> bit-identical to reference.
//   Code tile transposed in smem to [l][k] so LDS.128 yields 4 codes per l.
// ---------------------------------------------------------------------------
__global__ void __launch_bounds__(TPB2)
argmin_kernel(const float* __restrict__ ze, const float* __restrict__ emb,
              float* __restrict__ out_idx) {
    __shared__ float se[LD * KT];      // [l][k] transposed tile, 32 KB
    __shared__ float sen2[KT];

    const int tid = threadIdx.x;
    int n  = blockIdx.x * TPB2 + tid;   // row id (b,h,w)
    int b  = n >> 12;
    int hw = n & 4095;

    // Load zf row (ze[b][l][h][w], coalesced across hw), compute a = ||zf||^2
    // with separate mul/add rounding, and pack (zf[l], zf[l]) pairs.
    const float* zb = ze + (size_t)(b * LD) * HWD + hw;
    unsigned long long zz[LD];
    float a = 0.0f;
#pragma unroll
    for (int l = 0; l < LD; l++) {
        float v = zb[(size_t)l * HWD];
        a = __fadd_rn(a, __fmul_rn(v, v));
        unsigned int u = __float_as_uint(v);
        PACK2(zz[l], u, u);
    }

    float best = __int_as_float(0x7f800000);  // +inf
    int   bi   = 0;

    for (int t = 0; t < KCODES / KT; t++) {
        __syncthreads();
        // Transposed cooperative tile load: thread handles codes c=tid, tid+64.
        // STS bank = (l*128 + c) % 32 = c % 32 -> lanes 0..31 conflict-free.
        {
#pragma unroll
            for (int h = 0; h < 2; h++) {
                int c = tid + h * TPB2;
                const float4* src = (const float4*)(emb + (size_t)(t * KT + c) * LD);
#pragma unroll
                for (int j = 0; j < LD / 4; j++) {
                    float4 v = src[j];
                    se[(4 * j + 0) * KT + c] = v.x;
                    se[(4 * j + 1) * KT + c] = v.y;
                    se[(4 * j + 2) * KT + c] = v.z;
                    se[(4 * j + 3) * KT + c] = v.w;
                }
                sen2[c] = g_en2[t * KT + c];
            }
        }
        __syncthreads();

        // 4 codes per group: two f32x2 accumulator chains (ILP 2).
        for (int kk = 0; kk < KT; kk += 4) {
            unsigned long long m01 = 0ull, m23 = 0ull;
            const float4* col = (const float4*)(se + kk);   // stride KT/4 float4
#pragma unroll
            for (int l = 0; l < LD; l++) {
                float4 v = col[l * (KT / 4)];               // codes kk..kk+3 at l
                unsigned long long e01, e23;
                unsigned int vx = __float_as_uint(v.x), vy = __float_as_uint(v.y);
                unsigned int vz = __float_as_uint(v.z), vw = __float_as_uint(v.w);
                PACK2(e01, vx, vy);
                PACK2(e23, vz, vw);
                FMA_F32X2(m01, zz[l], e01, m01);
                FMA_F32X2(m23, zz[l], e23, m23);
            }
            unsigned int u0, u1, u2, u3;
            UNPACK2(u0, u1, m01);
            UNPACK2(u2, u3, m23);
            float m0 = __uint_as_float(u0), m1 = __uint_as_float(u1);
            float m2 = __uint_as_float(u2), m3 = __uint_as_float(u3);
            // d = fl( fl(a + en2) + (-2*m) ); -2*m exact in fp32
            float d0 = __fadd_rn(__fadd_rn(a, sen2[kk + 0]), __fmul_rn(-2.0f, m0));
            float d1 = __fadd_rn(__fadd_rn(a, sen2[kk + 1]), __fmul_rn(-2.0f, m1));
            float d2 = __fadd_rn(__fadd_rn(a, sen2[kk + 2]), __fmul_rn(-2.0f, m2));
            float d3 = __fadd_rn(__fadd_rn(a, sen2[kk + 3]), __fmul_rn(-2.0f, m3));
            int k0 = t * KT + kk;
            if (d0 < best) { best = d0; bi = k0;     }
            if (d1 < best) { best = d1; bi = k0 + 1; }
            if (d2 < best) { best = d2; bi = k0 + 2; }
            if (d3 < best) { best = d3; bi = k0 + 3; }
        }
    }

    g_idx[n]   = bi;
    out_idx[n] = (float)bi;   // idx output region
}

// ---------------------------------------------------------------------------
// K3: gather z_q (float4), emit z_q_st = ze + (z_q - ze) in reference op
// order, block-reduce fl32((z_q-ze)^2) in double, one atomicAdd per block.
// ---------------------------------------------------------------------------
__global__ void __launch_bounds__(256)
gather_kernel(const float* __restrict__ ze, const float* __restrict__ emb,
              float* __restrict__ out) {
    __shared__ double swarp[8];
    int i   = (blockIdx.x * 256 + threadIdx.x) * 4;   // linear (b,l,h,w)
    int b   = i >> 18;                                // 64*4096 per b
    int rem = i & 262143;
    int l   = rem >> 12;
    int hw  = rem & 4095;
    int n   = (b << 12) | hw;

    int4   ki = *(const int4*)(g_idx + n);
    float4 ze4 = *(const float4*)(ze + i);
    float t0 = __fadd_rn(emb[ki.x * LD + l], -ze4.x);
    float t1 = __fadd_rn(emb[ki.y * LD + l], -ze4.y);
    float t2 = __fadd_rn(emb[ki.z * LD + l], -ze4.z);
    float t3 = __fadd_rn(emb[ki.w * LD + l], -ze4.w);
    float4 o4;
    o4.x = __fadd_rn(ze4.x, t0);
    o4.y = __fadd_rn(ze4.y, t1);
    o4.z = __fadd_rn(ze4.z, t2);
    o4.w = __fadd_rn(ze4.w, t3);
    *(float4*)(out + i) = o4;

    double s = (double)__fmul_rn(t0, t0) + (double)__fmul_rn(t1, t1)
             + (double)__fmul_rn(t2, t2) + (double)__fmul_rn(t3, t3);
#pragma unroll
    for (int o = 16; o > 0; o >>= 1)
        s += __shfl_down_sync(0xffffffffu, s, o);
    int wid = threadIdx.x >> 5, lid = threadIdx.x & 31;
    if (lid == 0) swarp[wid] = s;
    __syncthreads();
    if (wid == 0) {
        double v = (lid < 8) ? swarp[lid] : 0.0;
#pragma unroll
        for (int o = 4; o > 0; o >>= 1)
            v += __shfl_down_sync(0xffffffffu, v, o);
        if (lid == 0) atomicAdd(&g_loss, v);
    }
}

// ---------------------------------------------------------------------------
// K4: finalize loss = 1.25 * mean((z_q - ze)^2)
// ---------------------------------------------------------------------------
__global__ void loss_kernel(float* __restrict__ out) {
    out[ELEMS] = (float)(g_loss / (double)ELEMS * 1.25);
}

// ---------------------------------------------------------------------------
// Launch. Outputs concatenated: [z_q_st (4194304)] [loss (1)] [idx (65536)]
// ---------------------------------------------------------------------------
extern "C" void kernel_launch(void* const* d_in, const int* in_sizes, int n_in,
                              void* d_out, int out_size) {
    const float* ze  = (const float*)d_in[0];   // 4194304
    const float* emb = (const float*)d_in[1];   // 65536
    float* out = (float*)d_out;
    float* out_idx = out + ELEMS + 1;

    en2_kernel   <<<(KCODES + 255) / 256, 256>>>(emb);
    argmin_kernel<<<NROWS / TPB2, TPB2>>>(ze, emb, out_idx);
    gather_kernel<<<ELEMS / (256 * 4), 256>>>(ze, emb, out);
    loss_kernel  <<<1, 1>>>(out);
}

// round 6
// speedup vs baseline: 1.9985x; 1.6139x over previous
#include <cuda_runtime.h>
#include <cstdint>

// Problem constants
#define LD      64
#define HWD     4096
#define NROWS   65536
#define KCODES  1024
#define ELEMS   4194304
#define LPAD    136         // padded smem row stride (floats) -> conflict-free frags
#define CAND    32          // max candidates per row (overflow -> exact full scan)
#define TAU     2e-3f       // screening slack; bound needs only ~2.3e-4

// Scratch (static device allocations only)
__device__ int    g_idx[NROWS];
__device__ float  g_en2[KCODES];
__device__ double g_loss;

// Order-preserving float<->uint key for atomicMin over signed floats
__device__ __forceinline__ unsigned fkey(float x) {
    unsigned u = __float_as_uint(x);
    return (u & 0x80000000u) ? ~u : (u | 0x80000000u);
}
__device__ __forceinline__ float funkey(unsigned k) {
    unsigned u = (k & 0x80000000u) ? (k ^ 0x80000000u) : ~k;
    return __uint_as_float(u);
}

// Warp-level tf32 MMA, D = A(16x8) * B(8x8) + D, fp32 accumulate.
#define MMA_TF32(c0,c1,c2,c3, a0,a1,a2,a3, b0,b1) \
    asm volatile("mma.sync.aligned.m16n8k8.row.col.f32.tf32.tf32.f32 " \
        "{%0,%1,%2,%3}, {%4,%5,%6,%7}, {%8,%9}, {%0,%1,%2,%3};" \
        : "+f"(c0), "+f"(c1), "+f"(c2), "+f"(c3) \
        : "r"(a0), "r"(a1), "r"(a2), "r"(a3), "r"(b0), "r"(b1))

// ---------------------------------------------------------------------------
// K1: exact per-code squared norms (separate mul/add, sequential order —
// matches jnp.sum(emb*emb, axis=1) bit-exactly). Zeroes loss accumulator.
// ---------------------------------------------------------------------------
__global__ void en2_kernel(const float* __restrict__ emb) {
    int k = blockIdx.x * blockDim.x + threadIdx.x;
    if (k == 0) g_loss = 0.0;
    if (k < KCODES) {
        const float* e = emb + k * LD;
        float s = 0.0f;
#pragma unroll
        for (int l = 0; l < LD; l++)
            s = __fadd_rn(s, __fmul_rn(e[l], e[l]));
        g_en2[k] = s;
    }
}

// ---------------------------------------------------------------------------
// K2: tensor-core screen + exact recheck.
//   Block = 128 rows. 8 warps in 4x2 (M x N) layout: warp tile 32 rows x 64
//   codes per 128-code tile. tf32 mma computes m~ for screening only; the
//   final argmin is decided by bit-exact fp32 sequential chains on the
//   candidate set {k : s~_k <= rowmin~ + TAU}, which provably contains the
//   reference argmin.
// ---------------------------------------------------------------------------
__global__ void __launch_bounds__(256, 2)
screen_kernel(const float* __restrict__ ze, const float* __restrict__ emb,
              float* __restrict__ out_idx) {
    extern __shared__ unsigned char smem_raw[];
    float*    szf     = (float*)smem_raw;            // [64][LPAD] zf tile (l-major)
    float*    sc      = szf + 64 * LPAD;             // [64][LPAD] code tile (l-major)
    float*    sen2t   = sc + 64 * LPAD;              // [128] exact ||e||^2 tile
    unsigned* sminkey = (unsigned*)(sen2t + 128);    // [128] per-row approx-min key
    int*      ccnt    = (int*)(sminkey + 128);       // [128]
    int*      cand    = ccnt + 128;                  // [128][CAND]

    const int tid  = threadIdx.x;
    const int lane = tid & 31, wid = tid >> 5;
    const int rowbase = blockIdx.x * 128;
    const int b   = rowbase >> 12;                   // all 128 rows share b
    const int hw0 = rowbase & 4095;

    if (tid < 128) { sminkey[tid] = 0xFFFFFFFFu; ccnt[tid] = 0; }

    // Load zf tile: ze[b][l][hw]  ->  szf[l][r]   (coalesced, conflict-free STS)
    for (int i = tid; i < 64 * 128; i += 256) {
        int l = i >> 7, r = i & 127;
        szf[l * LPAD + r] = ze[((size_t)(b * LD + l) << 12) + hw0 + r];
    }

    // Warp tiling
    const int mb = (wid >> 1) << 5;    // row base of this warp (0/32/64/96)
    const int nh = (wid & 1) << 6;     // code half within tile (0/64)
    const int q  = lane >> 2;          // 0..7
    const int tg = lane & 3;           // 0..3
    const int r0 = mb + q, r1 = r0 + 8, r2 = r0 + 16, r3 = r0 + 24;

    for (int ct = 0; ct < 8; ct++) {
        __syncthreads();   // sc/sen2t safe to overwrite (prev phase-b done)
        // Load code tile ct: emb[ct*128+c][l] -> sc[l][c], plus exact en2
        {
            int c = tid & 127, half = tid >> 7;
            const float4* src =
                (const float4*)(emb + ((size_t)(ct * 128 + c)) * LD + half * 32);
#pragma unroll
            for (int j = 0; j < 8; j++) {
                float4 v = src[j];
                int l = half * 32 + j * 4;
                sc[(l + 0) * LPAD + c] = v.x;
                sc[(l + 1) * LPAD + c] = v.y;
                sc[(l + 2) * LPAD + c] = v.z;
                sc[(l + 3) * LPAD + c] = v.w;
            }
            if (tid < 128) sen2t[tid] = g_en2[ct * 128 + tid];
        }
        __syncthreads();

        // acc[ns][0..3] = mf0 (rows r0,r1), acc[ns][4..7] = mf1 (rows r2,r3)
        float acc[8][8];
#pragma unroll
        for (int ns = 0; ns < 8; ns++)
#pragma unroll
            for (int j = 0; j < 8; j++) acc[ns][j] = 0.0f;

#pragma unroll
        for (int ks = 0; ks < 8; ks++) {
            int l0 = ks * 8 + tg;
            // A fragments (raw fp32 bits as tf32; HW truncation is fine)
            unsigned a00 = __float_as_uint(szf[l0 * LPAD + mb + q]);
            unsigned a01 = __float_as_uint(szf[l0 * LPAD + mb + q + 8]);
            unsigned a02 = __float_as_uint(szf[(l0 + 4) * LPAD + mb + q]);
            unsigned a03 = __float_as_uint(szf[(l0 + 4) * LPAD + mb + q + 8]);
            unsigned a10 = __float_as_uint(szf[l0 * LPAD + mb + q + 16]);
            unsigned a11 = __float_as_uint(szf[l0 * LPAD + mb + q + 24]);
            unsigned a12 = __float_as_uint(szf[(l0 + 4) * LPAD + mb + q + 16]);
            unsigned a13 = __float_as_uint(szf[(l0 + 4) * LPAD + mb + q + 24]);
#pragma unroll
            for (int ns = 0; ns < 8; ns++) {
                int cb = nh + ns * 8;
                unsigned b0 = __float_as_uint(sc[l0 * LPAD + cb + q]);
                unsigned b1 = __float_as_uint(sc[(l0 + 4) * LPAD + cb + q]);
                MMA_TF32(acc[ns][0], acc[ns][1], acc[ns][2], acc[ns][3],
                         a00, a01, a02, a03, b0, b1);
                MMA_TF32(acc[ns][4], acc[ns][5], acc[ns][6], acc[ns][7],
                         a10, a11, a12, a13, b0, b1);
            }
        }

        // Phase a: s~ = en2 - 2 m~ (in place), per-row min -> smem atomicMin
        float m0 = __int_as_float(0x7f800000), m1 = m0, m2 = m0, m3 = m0;
#pragma unroll
        for (int ns = 0; ns < 8; ns++) {
            int cl = nh + ns * 8 + 2 * tg;
            float e0 = sen2t[cl], e1 = sen2t[cl + 1];
            acc[ns][0] = e0 - 2.0f * acc[ns][0];
            acc[ns][1] = e1 - 2.0f * acc[ns][1];
            acc[ns][2] = e0 - 2.0f * acc[ns][2];
            acc[ns][3] = e1 - 2.0f * acc[ns][3];
            acc[ns][4] = e0 - 2.0f * acc[ns][4];
            acc[ns][5] = e1 - 2.0f * acc[ns][5];
            acc[ns][6] = e0 - 2.0f * acc[ns][6];
            acc[ns][7] = e1 - 2.0f * acc[ns][7];
            m0 = fminf(m0, fminf(acc[ns][0], acc[ns][1]));
            m1 = fminf(m1, fminf(acc[ns][2], acc[ns][3]));
            m2 = fminf(m2, fminf(acc[ns][4], acc[ns][5]));
            m3 = fminf(m3, fminf(acc[ns][6], acc[ns][7]));
        }
        atomicMin(&sminkey[r0], fkey(m0));
        atomicMin(&sminkey[r1], fkey(m1));
        atomicMin(&sminkey[r2], fkey(m2));
        atomicMin(&sminkey[r3], fkey(m3));
        __syncthreads();

        // Phase b: collect candidates vs running min (over-collects -> safe)
        float t0 = funkey(sminkey[r0]) + TAU;
        float t1 = funkey(sminkey[r1]) + TAU;
        float t2 = funkey(sminkey[r2]) + TAU;
        float t3 = funkey(sminkey[r3]) + TAU;
#pragma unroll
        for (int ns = 0; ns < 8; ns++) {
            int k0 = ct * 128 + nh + ns * 8 + 2 * tg;
#pragma unroll
            for (int j = 0; j < 8; j++) {
                int   row = (j < 2) ? r0 : (j < 4) ? r1 : (j < 6) ? r2 : r3;
                float th  = (j < 2) ? t0 : (j < 4) ? t1 : (j < 6) ? t2 : t3;
                if (acc[ns][j] <= th) {
                    int c = atomicAdd(&ccnt[row], 1);
                    if (c < CAND) cand[row * CAND + c] = k0 + (j & 1);
                }
            }
        }
    }
    __syncthreads();

    // Exact phase: one thread per row replays bit-exact reference arithmetic.
    if (tid < 128) {
        int r = tid;
        float a = 0.0f;
#pragma unroll
        for (int l = 0; l < LD; l++) {
            float v = szf[l * LPAD + r];
            a = __fadd_rn(a, __fmul_rn(v, v));
        }
        float best = __int_as_float(0x7f800000);
        int   bi   = 0;
        int   cnt  = ccnt[r];
        if (cnt <= CAND) {
            for (int j = 0; j < cnt; j++) {
                int k = cand[r * CAND + j];
                const float* e = emb + (size_t)k * LD;
                float m = 0.0f;
#pragma unroll
                for (int l = 0; l < LD; l++)
                    m = __fmaf_rn(szf[l * LPAD + r], __ldg(e + l), m);
                float d = __fadd_rn(__fadd_rn(a, __ldg(&g_en2[k])),
                                    __fmul_rn(-2.0f, m));
                if (d < best || (d == best && k < bi)) { best = d; bi = k; }
            }
        } else {  // overflow fallback: exact full scan (never expected)
            for (int k = 0; k < KCODES; k++) {
                const float* e = emb + (size_t)k * LD;
                float m = 0.0f;
#pragma unroll
                for (int l = 0; l < LD; l++)
                    m = __fmaf_rn(szf[l * LPAD + r], __ldg(e + l), m);
                float d = __fadd_rn(__fadd_rn(a, __ldg(&g_en2[k])),
                                    __fmul_rn(-2.0f, m));
                if (d < best) { best = d; bi = k; }
            }
        }
        int n = rowbase + r;
        g_idx[n]   = bi;
        out_idx[n] = (float)bi;
    }
}

// ---------------------------------------------------------------------------
// K3: gather z_q (float4), z_q_st = ze + (z_q - ze) in reference op order,
// block-reduce fl32((z_q-ze)^2) in double, one atomicAdd per block.
// ---------------------------------------------------------------------------
__global__ void __launch_bounds__(256)
gather_kernel(const float* __restrict__ ze, const float* __restrict__ emb,
              float* __restrict__ out) {
    __shared__ double swarp[8];
    int i   = (blockIdx.x * 256 + threadIdx.x) * 4;
    int b   = i >> 18;
    int rem = i & 262143;
    int l   = rem >> 12;
    int hw  = rem & 4095;
    int n   = (b << 12) | hw;

    int4   ki  = *(const int4*)(g_idx + n);
    float4 ze4 = *(const float4*)(ze + i);
    float t0 = __fadd_rn(emb[ki.x * LD + l], -ze4.x);
    float t1 = __fadd_rn(emb[ki.y * LD + l], -ze4.y);
    float t2 = __fadd_rn(emb[ki.z * LD + l], -ze4.z);
    float t3 = __fadd_rn(emb[ki.w * LD + l], -ze4.w);
    float4 o4;
    o4.x = __fadd_rn(ze4.x, t0);
    o4.y = __fadd_rn(ze4.y, t1);
    o4.z = __fadd_rn(ze4.z, t2);
    o4.w = __fadd_rn(ze4.w, t3);
    *(float4*)(out + i) = o4;

    double s = (double)__fmul_rn(t0, t0) + (double)__fmul_rn(t1, t1)
             + (double)__fmul_rn(t2, t2) + (double)__fmul_rn(t3, t3);
#pragma unroll
    for (int o = 16; o > 0; o >>= 1)
        s += __shfl_down_sync(0xffffffffu, s, o);
    int w = threadIdx.x >> 5, lid = threadIdx.x & 31;
    if (lid == 0) swarp[w] = s;
    __syncthreads();
    if (w == 0) {
        double v = (lid < 8) ? swarp[lid] : 0.0;
#pragma unroll
        for (int o = 4; o > 0; o >>= 1)
            v += __shfl_down_sync(0xffffffffu, v, o);
        if (lid == 0) atomicAdd(&g_loss, v);
    }
}

__global__ void loss_kernel(float* __restrict__ out) {
    out[ELEMS] = (float)(g_loss / (double)ELEMS * 1.25);
}

// ---------------------------------------------------------------------------
// Launch. Outputs: [z_q_st (4194304)] [loss (1)] [idx (65536)]
// ---------------------------------------------------------------------------
#define SMEM_SCREEN ((64 * LPAD * 2 + 128) * 4 + 128 * 4 + 128 * 4 + 128 * CAND * 4)

extern "C" void kernel_launch(void* const* d_in, const int* in_sizes, int n_in,
                              void* d_out, int out_size) {
    const float* ze  = (const float*)d_in[0];
    const float* emb = (const float*)d_in[1];
    float* out     = (float*)d_out;
    float* out_idx = out + ELEMS + 1;

    cudaFuncSetAttribute(screen_kernel,
                         cudaFuncAttributeMaxDynamicSharedMemorySize,
                         SMEM_SCREEN);

    en2_kernel   <<<(KCODES + 255) / 256, 256>>>(emb);
    screen_kernel<<<NROWS / 128, 256, SMEM_SCREEN>>>(ze, emb, out_idx);
    gather_kernel<<<ELEMS / (256 * 4), 256>>>(ze, emb, out);
    loss_kernel  <<<1, 1>>>(out);
}

// round 7
// speedup vs baseline: 2.0631x; 1.0323x over previous
#include <cuda_runtime.h>
#include <cstdint>

// Problem constants
#define LD      64
#define HWD     4096
#define NROWS   65536
#define KCODES  1024
#define ELEMS   4194304
#define LPAD    136         // padded stride (words) -> conflict-free fragment LDS
#define CAND    32          // max candidates per row (overflow -> exact full scan)
#define TAU     2e-3f       // screening slack; bf16 worst-case error ~6.3e-4

// Scratch (static device allocations only)
__device__ int    g_idx[NROWS];
__device__ float  g_en2[KCODES];
__device__ double g_loss;

// Order-preserving float<->uint key for atomicMin over signed floats
__device__ __forceinline__ unsigned fkey(float x) {
    unsigned u = __float_as_uint(x);
    return (u & 0x80000000u) ? ~u : (u | 0x80000000u);
}
__device__ __forceinline__ float funkey(unsigned k) {
    unsigned u = (k & 0x80000000u) ? (k ^ 0x80000000u) : ~k;
    return __uint_as_float(u);
}

// Pack two fp32 -> bf16x2 (lo = first/even-k element, hi = second/odd-k)
__device__ __forceinline__ unsigned pack_bf2(float lo, float hi) {
    unsigned r;
    asm("cvt.rn.bf16x2.f32 %0, %1, %2;" : "=r"(r) : "f"(hi), "f"(lo));
    return r;
}

// Warp-level bf16 MMA, D(16x8,f32) += A(16x16) * B(16x8)
#define MMA_BF16(c0,c1,c2,c3, a0,a1,a2,a3, b0,b1) \
    asm volatile("mma.sync.aligned.m16n8k16.row.col.f32.bf16.bf16.f32 " \
        "{%0,%1,%2,%3}, {%4,%5,%6,%7}, {%8,%9}, {%0,%1,%2,%3};" \
        : "+f"(c0), "+f"(c1), "+f"(c2), "+f"(c3) \
        : "r"(a0), "r"(a1), "r"(a2), "r"(a3), "r"(b0), "r"(b1))

// ---------------------------------------------------------------------------
// K1: exact per-code squared norms (separate mul/add, sequential order —
// matches jnp.sum(emb*emb, axis=1) bit-exactly). Zeroes loss accumulator.
// ---------------------------------------------------------------------------
__global__ void en2_kernel(const float* __restrict__ emb) {
    int k = blockIdx.x * blockDim.x + threadIdx.x;
    if (k == 0) g_loss = 0.0;
    if (k < KCODES) {
        const float* e = emb + k * LD;
        float s = 0.0f;
#pragma unroll
        for (int l = 0; l < LD; l++)
            s = __fadd_rn(s, __fmul_rn(e[l], e[l]));
        g_en2[k] = s;
    }
}

// ---------------------------------------------------------------------------
// K2: bf16 tensor-core screen + bit-exact fp32 recheck.
//   Block = 128 rows, 8 warps in 4x2 (M x N): warp tile 32 rows x 64 codes.
//   A (zf) fragments hoisted out of the code-tile loop (invariant).
//   Screen selects {k : s~_k <= rowmin~ + TAU} (provably contains argmin);
//   exact phase replays reference fp32 arithmetic to decide.
// ---------------------------------------------------------------------------
__global__ void __launch_bounds__(256, 2)
screen_kernel(const float* __restrict__ ze, const float* __restrict__ emb,
              float* __restrict__ out_idx) {
    extern __shared__ unsigned char smem_raw[];
    float*    szf     = (float*)smem_raw;            // [64][LPAD] fp32 zf (exact phase)
    unsigned* szb     = (unsigned*)(szf + 64 * LPAD);    // [32][LPAD] bf16x2 zf pairs
    unsigned* scb     = szb + 32 * LPAD;                 // [32][LPAD] bf16x2 code pairs
    float*    sen2t   = (float*)(scb + 32 * LPAD);       // [128] exact ||e||^2 tile
    unsigned* sminkey = (unsigned*)(sen2t + 128);        // [128] per-row approx-min key
    int*      ccnt    = (int*)(sminkey + 128);           // [128]
    int*      cand    = ccnt + 128;                      // [128][CAND]

    const int tid  = threadIdx.x;
    const int lane = tid & 31, wid = tid >> 5;
    const int rowbase = blockIdx.x * 128;
    const int b   = rowbase >> 12;                   // all 128 rows share b
    const int hw0 = rowbase & 4095;

    if (tid < 128) { sminkey[tid] = 0xFFFFFFFFu; ccnt[tid] = 0; }

    // Load zf tile: fp32 into szf[l][r] AND packed bf16x2 k-pairs into szb.
    for (int i = tid; i < 32 * 128; i += 256) {
        int l2 = i >> 7, r = i & 127;
        float f0 = ze[((size_t)(b * LD + 2 * l2    ) << 12) + hw0 + r];
        float f1 = ze[((size_t)(b * LD + 2 * l2 + 1) << 12) + hw0 + r];
        szf[(2 * l2    ) * LPAD + r] = f0;
        szf[(2 * l2 + 1) * LPAD + r] = f1;
        szb[l2 * LPAD + r] = pack_bf2(f0, f1);
    }
    __syncthreads();

    // Warp tiling
    const int mb = (wid >> 1) << 5;    // row base (0/32/64/96)
    const int nh = (wid & 1) << 6;     // code half (0/64)
    const int q  = lane >> 2;          // 0..7
    const int tg = lane & 3;           // 0..3
    const int r0 = mb + q, r1 = r0 + 8, r2 = r0 + 16, r3 = r0 + 24;

    // Hoist all A fragments (invariant across code tiles): 4 ks x 8 regs.
    unsigned Af[4][8];
#pragma unroll
    for (int ks = 0; ks < 4; ks++) {
        int p = ks * 8 + tg;
        Af[ks][0] = szb[(p    ) * LPAD + mb + q];
        Af[ks][1] = szb[(p    ) * LPAD + mb + q + 8];
        Af[ks][2] = szb[(p + 4) * LPAD + mb + q];
        Af[ks][3] = szb[(p + 4) * LPAD + mb + q + 8];
        Af[ks][4] = szb[(p    ) * LPAD + mb + q + 16];
        Af[ks][5] = szb[(p    ) * LPAD + mb + q + 24];
        Af[ks][6] = szb[(p + 4) * LPAD + mb + q + 16];
        Af[ks][7] = szb[(p + 4) * LPAD + mb + q + 24];
    }

    for (int ct = 0; ct < 8; ct++) {
        __syncthreads();   // scb/sen2t safe to overwrite
        // Load code tile: emb[ct*128+c][l] -> scb[l/2][c] (bf16x2 k-pairs)
        {
            int c = tid & 127, half = tid >> 7;
            const float4* src =
                (const float4*)(emb + ((size_t)(ct * 128 + c)) * LD + half * 32);
#pragma unroll
            for (int j = 0; j < 8; j++) {
                float4 v = src[j];
                int l2 = half * 16 + j * 2;
                scb[(l2    ) * LPAD + c] = pack_bf2(v.x, v.y);
                scb[(l2 + 1) * LPAD + c] = pack_bf2(v.z, v.w);
            }
            if (tid < 128) sen2t[tid] = g_en2[ct * 128 + tid];
        }
        __syncthreads();

        // acc[ns][0..3] rows r0,r1 ; acc[ns][4..7] rows r2,r3
        float acc[8][8];
#pragma unroll
        for (int ns = 0; ns < 8; ns++)
#pragma unroll
            for (int j = 0; j < 8; j++) acc[ns][j] = 0.0f;

#pragma unroll
        for (int ks = 0; ks < 4; ks++) {
            int p = ks * 8 + tg;
#pragma unroll
            for (int ns = 0; ns < 8; ns++) {
                int cb = nh + ns * 8;
                unsigned b0 = scb[(p    ) * LPAD + cb + q];
                unsigned b1 = scb[(p + 4) * LPAD + cb + q];
                MMA_BF16(acc[ns][0], acc[ns][1], acc[ns][2], acc[ns][3],
                         Af[ks][0], Af[ks][1], Af[ks][2], Af[ks][3], b0, b1);
                MMA_BF16(acc[ns][4], acc[ns][5], acc[ns][6], acc[ns][7],
                         Af[ks][4], Af[ks][5], Af[ks][6], Af[ks][7], b0, b1);
            }
        }

        // Phase a: s~ = en2 - 2 m~, per-row min via smem atomicMin
        float m0 = __int_as_float(0x7f800000), m1 = m0, m2 = m0, m3 = m0;
#pragma unroll
        for (int ns = 0; ns < 8; ns++) {
            int cl = nh + ns * 8 + 2 * tg;
            float e0 = sen2t[cl], e1 = sen2t[cl + 1];
            acc[ns][0] = e0 - 2.0f * acc[ns][0];
            acc[ns][1] = e1 - 2.0f * acc[ns][1];
            acc[ns][2] = e0 - 2.0f * acc[ns][2];
            acc[ns][3] = e1 - 2.0f * acc[ns][3];
            acc[ns][4] = e0 - 2.0f * acc[ns][4];
            acc[ns][5] = e1 - 2.0f * acc[ns][5];
            acc[ns][6] = e0 - 2.0f * acc[ns][6];
            acc[ns][7] = e1 - 2.0f * acc[ns][7];
            m0 = fminf(m0, fminf(acc[ns][0], acc[ns][1]));
            m1 = fminf(m1, fminf(acc[ns][2], acc[ns][3]));
            m2 = fminf(m2, fminf(acc[ns][4], acc[ns][5]));
            m3 = fminf(m3, fminf(acc[ns][6], acc[ns][7]));
        }
        atomicMin(&sminkey[r0], fkey(m0));
        atomicMin(&sminkey[r1], fkey(m1));
        atomicMin(&sminkey[r2], fkey(m2));
        atomicMin(&sminkey[r3], fkey(m3));
        __syncthreads();

        // Phase b: collect candidates vs running min (over-collects -> safe)
        float t0 = funkey(sminkey[r0]) + TAU;
        float t1 = funkey(sminkey[r1]) + TAU;
        float t2 = funkey(sminkey[r2]) + TAU;
        float t3 = funkey(sminkey[r3]) + TAU;
#pragma unroll
        for (int ns = 0; ns < 8; ns++) {
            int k0 = ct * 128 + nh + ns * 8 + 2 * tg;
#pragma unroll
            for (int j = 0; j < 8; j++) {
                int   row = (j < 2) ? r0 : (j < 4) ? r1 : (j < 6) ? r2 : r3;
                float th  = (j < 2) ? t0 : (j < 4) ? t1 : (j < 6) ? t2 : t3;
                if (acc[ns][j] <= th) {
                    int c = atomicAdd(&ccnt[row], 1);
                    if (c < CAND) cand[row * CAND + c] = k0 + (j & 1);
                }
            }
        }
    }
    __syncthreads();

    // Exact phase: one thread per row replays bit-exact reference arithmetic.
    if (tid < 128) {
        int r = tid;
        float a = 0.0f;
#pragma unroll
        for (int l = 0; l < LD; l++) {
            float v = szf[l * LPAD + r];
            a = __fadd_rn(a, __fmul_rn(v, v));
        }
        float best = __int_as_float(0x7f800000);
        int   bi   = 0;
        int   cnt  = ccnt[r];
        if (cnt <= CAND) {
            for (int j = 0; j < cnt; j++) {
                int k = cand[r * CAND + j];
                const float* e = emb + (size_t)k * LD;
                float m = 0.0f;
#pragma unroll
                for (int l = 0; l < LD; l++)
                    m = __fmaf_rn(szf[l * LPAD + r], __ldg(e + l), m);
                float d = __fadd_rn(__fadd_rn(a, __ldg(&g_en2[k])),
                                    __fmul_rn(-2.0f, m));
                if (d < best || (d == best && k < bi)) { best = d; bi = k; }
            }
        } else {  // overflow fallback: exact full scan (never expected)
            for (int k = 0; k < KCODES; k++) {
                const float* e = emb + (size_t)k * LD;
                float m = 0.0f;
#pragma unroll
                for (int l = 0; l < LD; l++)
                    m = __fmaf_rn(szf[l * LPAD + r], __ldg(e + l), m);
                float d = __fadd_rn(__fadd_rn(a, __ldg(&g_en2[k])),
                                    __fmul_rn(-2.0f, m));
                if (d < best) { best = d; bi = k; }
            }
        }
        int n = rowbase + r;
        g_idx[n]   = bi;
        out_idx[n] = (float)bi;
    }
}

// ---------------------------------------------------------------------------
// K3: gather z_q (float4), z_q_st = ze + (z_q - ze) in reference op order,
// block-reduce fl32((z_q-ze)^2) in double, one atomicAdd per block.
// ---------------------------------------------------------------------------
__global__ void __launch_bounds__(256)
gather_kernel(const float* __restrict__ ze, const float* __restrict__ emb,
              float* __restrict__ out) {
    __shared__ double swarp[8];
    int i   = (blockIdx.x * 256 + threadIdx.x) * 4;
    int b   = i >> 18;
    int rem = i & 262143;
    int l   = rem >> 12;
    int hw  = rem & 4095;
    int n   = (b << 12) | hw;

    int4   ki  = *(const int4*)(g_idx + n);
    float4 ze4 = *(const float4*)(ze + i);
    float t0 = __fadd_rn(emb[ki.x * LD + l], -ze4.x);
    float t1 = __fadd_rn(emb[ki.y * LD + l], -ze4.y);
    float t2 = __fadd_rn(emb[ki.z * LD + l], -ze4.z);
    float t3 = __fadd_rn(emb[ki.w * LD + l], -ze4.w);
    float4 o4;
    o4.x = __fadd_rn(ze4.x, t0);
    o4.y = __fadd_rn(ze4.y, t1);
    o4.z = __fadd_rn(ze4.z, t2);
    o4.w = __fadd_rn(ze4.w, t3);
    *(float4*)(out + i) = o4;

    double s = (double)__fmul_rn(t0, t0) + (double)__fmul_rn(t1, t1)
             + (double)__fmul_rn(t2, t2) + (double)__fmul_rn(t3, t3);
#pragma unroll
    for (int o = 16; o > 0; o >>= 1)
        s += __shfl_down_sync(0xffffffffu, s, o);
    int w = threadIdx.x >> 5, lid = threadIdx.x & 31;
    if (lid == 0) swarp[w] = s;
    __syncthreads();
    if (w == 0) {
        double v = (lid < 8) ? swarp[lid] : 0.0;
#pragma unroll
        for (int o = 4; o > 0; o >>= 1)
            v += __shfl_down_sync(0xffffffffu, v, o);
        if (lid == 0) atomicAdd(&g_loss, v);
    }
}

__global__ void loss_kernel(float* __restrict__ out) {
    out[ELEMS] = (float)(g_loss / (double)ELEMS * 1.25);
}

// ---------------------------------------------------------------------------
// Launch. Outputs: [z_q_st (4194304)] [loss (1)] [idx (65536)]
// ---------------------------------------------------------------------------
#define SMEM_SCREEN (64 * LPAD * 4 + 32 * LPAD * 4 + 32 * LPAD * 4 \
                     + 128 * 4 + 128 * 4 + 128 * 4 + 128 * CAND * 4)

extern "C" void kernel_launch(void* const* d_in, const int* in_sizes, int n_in,
                              void* d_out, int out_size) {
    const float* ze  = (const float*)d_in[0];
    const float* emb = (const float*)d_in[1];
    float* out     = (float*)d_out;
    float* out_idx = out + ELEMS + 1;

    cudaFuncSetAttribute(screen_kernel,
                         cudaFuncAttributeMaxDynamicSharedMemorySize,
                         SMEM_SCREEN);

    en2_kernel   <<<(KCODES + 255) / 256, 256>>>(emb);
    screen_kernel<<<NROWS / 128, 256, SMEM_SCREEN>>>(ze, emb, out_idx);
    gather_kernel<<<ELEMS / (256 * 4), 256>>>(ze, emb, out);
    loss_kernel  <<<1, 1>>>(out);
}